// round 1
// baseline (speedup 1.0000x reference)
#include <cuda_runtime.h>

#define NN 8192
#define MM 8192
#define FD 128
#define ED 128
#define HD 64
#define NH 4

// ---- scratch (device globals; no allocations allowed) ----
__device__ float g_E1[(size_t)NH * MM * HD];   // 8 MB
__device__ float g_s[NH * NN];
__device__ float g_d[NH * MM];
__device__ float g_wfa[NH * FD];
__device__ float g_hp[(size_t)NN * HD];        // sum over heads of h_prime

// ---------------------------------------------------------------------------
// wfa[h,f] = sum_d Wf[h,f,d] * a[h,d]
__global__ void k_wfa(const float* __restrict__ Wf, const float* __restrict__ a) {
    int tid = threadIdx.x;
    if (tid < NH * FD) {
        int h = tid >> 7, f = tid & 127;
        const float* wp = Wf + ((size_t)h * FD + f) * HD;
        const float* ap = a + h * HD;
        float s = 0.f;
#pragma unroll 8
        for (int d = 0; d < HD; d++) s += wp[d] * ap[d];
        g_wfa[tid] = s;
    }
}

// s[h,n] = F0[n,:] . wfa[h,:]   (one warp per (h,n))
__global__ void k_s(const float* __restrict__ F0) {
    int warp = threadIdx.x >> 5, lane = threadIdx.x & 31;
    int gw = blockIdx.x * 8 + warp;          // 0..32767
    int n = gw & (NN - 1), h = gw >> 13;
    const float* fp = F0 + (size_t)n * FD;
    const float* wp = g_wfa + h * FD;
    float s = 0.f;
#pragma unroll
    for (int k = 0; k < 4; k++) {
        int f = lane + k * 32;
        s += fp[f] * wp[f];
    }
#pragma unroll
    for (int o = 16; o; o >>= 1) s += __shfl_xor_sync(0xffffffffu, s, o);
    if (lane == 0) g_s[h * NN + n] = s;
}

// E1[h,m,j] = sum_e E0[m,e]*We[h,e,j];  d[h,m] = E1[h,m,:] . a[h,:]
// One block handles 4 consecutive m rows for all heads. thread = (h, j).
__global__ __launch_bounds__(256) void k_e1(const float* __restrict__ E0,
                                            const float* __restrict__ We,
                                            const float* __restrict__ a) {
    __shared__ float E0s[4 * 128];
    __shared__ float dpart[8][4];
    int m0 = blockIdx.x * 4;
    int tid = threadIdx.x;
    for (int q = tid; q < 512; q += 256)
        E0s[q] = E0[(size_t)(m0 + (q >> 7)) * ED + (q & 127)];
    __syncthreads();

    int h = tid >> 6, j = tid & 63;
    float a0 = 0.f, a1 = 0.f, a2 = 0.f, a3 = 0.f;
    const float* Weh = We + ((size_t)h * ED) * HD + j;
#pragma unroll 4
    for (int e = 0; e < 128; e++) {
        float w = Weh[(size_t)e * HD];
        a0 += E0s[e] * w;
        a1 += E0s[128 + e] * w;
        a2 += E0s[256 + e] * w;
        a3 += E0s[384 + e] * w;
    }
    size_t base = (size_t)h * MM * HD + (size_t)m0 * HD + j;
    g_E1[base]          = a0;
    g_E1[base + HD]     = a1;
    g_E1[base + 2 * HD] = a2;
    g_E1[base + 3 * HD] = a3;

    float av = a[h * HD + j];
    float p0 = a0 * av, p1 = a1 * av, p2 = a2 * av, p3 = a3 * av;
#pragma unroll
    for (int o = 16; o; o >>= 1) {
        p0 += __shfl_xor_sync(0xffffffffu, p0, o);
        p1 += __shfl_xor_sync(0xffffffffu, p1, o);
        p2 += __shfl_xor_sync(0xffffffffu, p2, o);
        p3 += __shfl_xor_sync(0xffffffffu, p3, o);
    }
    int lane = tid & 31, w = tid >> 5;
    if (lane == 0) {
        dpart[w][0] = p0; dpart[w][1] = p1; dpart[w][2] = p2; dpart[w][3] = p3;
    }
    __syncthreads();
    if (tid < 16) {
        int h2 = tid >> 2, i2 = tid & 3;
        g_d[h2 * MM + m0 + i2] = dpart[2 * h2][i2] + dpart[2 * h2 + 1][i2];
    }
}

__global__ void k_zero() {
    size_t i = (size_t)blockIdx.x * blockDim.x + threadIdx.x;
    if (i < (size_t)NN * HD) g_hp[i] = 0.f;
}

// ---------------------------------------------------------------------------
// Main flash kernel: block = (64 rows, 1 head). Stream m in 64-tiles.
// W[n,m] = A[n,m] ? exp(lrelu(s_n + d_m)) : 0  (no max-sub needed: |s+d| < ~3)
// acc[n,:] += W tile @ E1 tile ;  Z[n] += row sums of W.
__global__ __launch_bounds__(256) void k_flash(const int* __restrict__ A) {
    __shared__ float Es[64 * 64];        // E1 tile [m][j]
    __shared__ float Wt[64 * 68];        // W transposed [m][n], padded
    __shared__ float s_sh[64];
    __shared__ float Z_sh[64];

    const int h = blockIdx.y;
    const int n0 = blockIdx.x * 64;
    const int tid = threadIdx.x;

    if (tid < 64) { s_sh[tid] = g_s[h * NN + n0 + tid]; Z_sh[tid] = 0.f; }

    float acc[4][4];
#pragma unroll
    for (int i = 0; i < 4; i++)
#pragma unroll
        for (int j = 0; j < 4; j++) acc[i][j] = 0.f;

    const int c = tid & 63, g = tid >> 6;       // W-generation mapping
    const int ty = tid >> 4, tx = tid & 15;     // GEMM mapping
    const float* E1h = g_E1 + (size_t)h * MM * HD;
    const float* dh  = g_d + h * MM;

    for (int m0 = 0; m0 < MM; m0 += 64) {
        __syncthreads();  // previous GEMM done with Es/Wt

        // load E1 tile (coalesced float4)
#pragma unroll
        for (int q = 0; q < 4; q++) {
            int idx = tid + q * 256;            // float4 index, 0..1023
            int row = idx >> 4, col = (idx & 15) << 2;
            *reinterpret_cast<float4*>(&Es[row * 64 + col]) =
                *reinterpret_cast<const float4*>(&E1h[(size_t)(m0 + row) * HD + col]);
        }

        float dval = dh[m0 + c];

        // generate W tile (transposed) + per-row Z
#pragma unroll
        for (int k = 0; k < 16; k++) {
            int r = g * 16 + k;                 // whole warp shares r
            int aval = A[(size_t)(n0 + r) * MM + m0 + c];
            float x = s_sh[r] + dval;
            x = fmaxf(x, 0.2f * x);             // leaky_relu(0.2)
            float w = (aval > 0) ? __expf(x) : 0.f;
            Wt[c * 68 + r] = w;
            float t = w;
#pragma unroll
            for (int o = 16; o; o >>= 1) t += __shfl_xor_sync(0xffffffffu, t, o);
            if ((tid & 31) == 0) atomicAdd(&Z_sh[r], t);
        }
        __syncthreads();

        // 4x4 register-tiled GEMM: acc += W^T(k, rows) * Es(k, cols)
#pragma unroll 8
        for (int k = 0; k < 64; k++) {
            float4 wv = *reinterpret_cast<const float4*>(&Wt[k * 68 + ty * 4]);
            float4 ev = *reinterpret_cast<const float4*>(&Es[k * 64 + tx * 4]);
            acc[0][0] += wv.x * ev.x; acc[0][1] += wv.x * ev.y;
            acc[0][2] += wv.x * ev.z; acc[0][3] += wv.x * ev.w;
            acc[1][0] += wv.y * ev.x; acc[1][1] += wv.y * ev.y;
            acc[1][2] += wv.y * ev.z; acc[1][3] += wv.y * ev.w;
            acc[2][0] += wv.z * ev.x; acc[2][1] += wv.z * ev.y;
            acc[2][2] += wv.z * ev.z; acc[2][3] += wv.z * ev.w;
            acc[3][0] += wv.w * ev.x; acc[3][1] += wv.w * ev.y;
            acc[3][2] += wv.w * ev.z; acc[3][3] += wv.w * ev.w;
        }
    }
    __syncthreads();

    // epilogue: h_prime = acc / Z, summed over heads into g_hp
#pragma unroll
    for (int i = 0; i < 4; i++) {
        int rr = ty * 4 + i;
        float inv = 1.0f / Z_sh[rr];
        float* hp = g_hp + (size_t)(n0 + rr) * HD + tx * 4;
#pragma unroll
        for (int j = 0; j < 4; j++) atomicAdd(&hp[j], acc[i][j] * inv);
    }
}

// out[n,:] = softmax(g_hp[n,:] / NH)  over 64 dims; one warp per row
__global__ void k_softmax(float* __restrict__ out) {
    int warp = threadIdx.x >> 5, lane = threadIdx.x & 31;
    int row = blockIdx.x * 8 + warp;
    float v0 = g_hp[(size_t)row * HD + lane] * 0.25f;
    float v1 = g_hp[(size_t)row * HD + 32 + lane] * 0.25f;
    float mx = fmaxf(v0, v1);
#pragma unroll
    for (int o = 16; o; o >>= 1) mx = fmaxf(mx, __shfl_xor_sync(0xffffffffu, mx, o));
    float e0 = __expf(v0 - mx), e1 = __expf(v1 - mx);
    float s = e0 + e1;
#pragma unroll
    for (int o = 16; o; o >>= 1) s += __shfl_xor_sync(0xffffffffu, s, o);
    float inv = 1.0f / s;
    out[(size_t)row * HD + lane]      = e0 * inv;
    out[(size_t)row * HD + 32 + lane] = e1 * inv;
}

// ---------------------------------------------------------------------------
extern "C" void kernel_launch(void* const* d_in, const int* in_sizes, int n_in,
                              void* d_out, int out_size) {
    const float* F0 = (const float*)d_in[0];
    const float* E0 = (const float*)d_in[1];
    const int*   A  = (const int*)d_in[2];
    const float* Wf = (const float*)d_in[3];
    const float* We = (const float*)d_in[4];
    const float* a  = (const float*)d_in[5];
    float* out = (float*)d_out;
    (void)in_sizes; (void)n_in; (void)out_size;

    k_wfa<<<1, 512>>>(Wf, a);
    k_s<<<NN * NH / 8 / 32 * 32 / 256 * 256 ? (NN * NH / 8) : 4096, 256>>>(F0);
    k_e1<<<MM / 4, 256>>>(E0, We, a);
    k_zero<<<(NN * HD + 1023) / 1024, 1024>>>();
    k_flash<<<dim3(NN / 64, NH), 256>>>(A);
    k_softmax<<<NN / 8, 256>>>(out);
}

// round 3
// speedup vs baseline: 6.3978x; 6.3978x over previous
#include <cuda_runtime.h>
#include <cuda_bf16.h>
#include <cstdint>

#define NN 8192
#define MM 8192
#define HD 64
#define NH 4
#define LOG2E 1.4426950408889634f

// ---- scratch (device globals; no allocations allowed) ----
__device__ float g_s[NH * NN];                              // pre-scaled by log2e
__device__ float g_d[NH * MM];                              // pre-scaled by log2e
__device__ float g_wfa[NH * 128];
__device__ __align__(16) __nv_bfloat16 g_E1b[(size_t)NH * MM * HD]; // [h][m][j] 4MB
__device__ uint32_t g_AbT[(size_t)(MM / 32) * NN];          // [m/32][n] 8MB
__device__ float g_np[NH][NN][HD];                          // per-head numerators 8MB
__device__ float g_zp[NH][NN];                              // per-head Z

__device__ __forceinline__ uint32_t smem_u32(const void* p) {
    uint32_t a;
    asm("{ .reg .u64 t; cvta.to.shared.u64 t, %1; cvt.u32.u64 %0, t; }" : "=r"(a) : "l"(p));
    return a;
}
__device__ __forceinline__ float ex2f(float x) {
    float r; asm("ex2.approx.ftz.f32 %0, %1;" : "=f"(r) : "f"(x)); return r;
}
#define MMA16816(acc, a0, a1, a2, a3, b0, b1)                                  \
    asm volatile("mma.sync.aligned.m16n8k16.row.col.f32.bf16.bf16.f32 "        \
                 "{%0,%1,%2,%3}, {%4,%5,%6,%7}, {%8,%9}, {%0,%1,%2,%3};"       \
                 : "+f"(acc[0]), "+f"(acc[1]), "+f"(acc[2]), "+f"(acc[3])      \
                 : "r"(a0), "r"(a1), "r"(a2), "r"(a3), "r"(b0), "r"(b1))

__device__ __forceinline__ uint32_t pack_bf2(float lo, float hi) {
    __nv_bfloat162 p = __floats2bfloat162_rn(lo, hi);
    return *reinterpret_cast<uint32_t*>(&p);
}

// ============================ stage kernels ============================
// Pack A into transposed bitmask: g_AbT[w][n], bit k = A[n][w*32+k] > 0
__global__ void k_pack(const int* __restrict__ A) {
    int lane = threadIdx.x & 31;
    int gw = (blockIdx.x * blockDim.x + threadIdx.x) >> 5;
    int nw = (gridDim.x * blockDim.x) >> 5;
    for (int idx = gw; idx < NN * (MM / 32); idx += nw) {
        int n = idx >> 8;            // MM/32 = 256
        int w = idx & 255;
        int v = A[(size_t)n * MM + w * 32 + lane];
        uint32_t bits = __ballot_sync(0xffffffffu, v > 0);
        if (lane == 0) g_AbT[(size_t)w * NN + n] = bits;
    }
}

// wfa[h,f] = sum_d Wf[h,f,d] * a[h,d]
__global__ void k_wfa(const float* __restrict__ Wf, const float* __restrict__ a) {
    int tid = threadIdx.x;
    if (tid < NH * 128) {
        int h = tid >> 7, f = tid & 127;
        const float* wp = Wf + ((size_t)h * 128 + f) * HD;
        const float* ap = a + h * HD;
        float s = 0.f;
#pragma unroll 8
        for (int d = 0; d < HD; d++) s += wp[d] * ap[d];
        g_wfa[tid] = s;
    }
}

// s[h,n] = (F0[n,:] . wfa[h,:]) * log2e
__global__ void k_s(const float* __restrict__ F0) {
    int warp = threadIdx.x >> 5, lane = threadIdx.x & 31;
    int gw = blockIdx.x * 8 + warp;
    int n = gw & (NN - 1), h = gw >> 13;
    const float* fp = F0 + (size_t)n * 128;
    const float* wp = g_wfa + h * 128;
    float s = 0.f;
#pragma unroll
    for (int k = 0; k < 4; k++) { int f = lane + k * 32; s += fp[f] * wp[f]; }
#pragma unroll
    for (int o = 16; o; o >>= 1) s += __shfl_xor_sync(0xffffffffu, s, o);
    if (lane == 0) g_s[h * NN + n] = s * LOG2E;
}

// E1b[h][m][j] (bf16, m-major) and d[h][m] * log2e
__global__ __launch_bounds__(256) void k_e1(const float* __restrict__ E0,
                                            const float* __restrict__ We,
                                            const float* __restrict__ a) {
    __shared__ float E0s[4 * 128];
    __shared__ float dpart[8][4];
    int m0 = blockIdx.x * 4;
    int tid = threadIdx.x;
    for (int q = tid; q < 512; q += 256)
        E0s[q] = E0[(size_t)(m0 + (q >> 7)) * 128 + (q & 127)];
    __syncthreads();

    int h = tid >> 6, j = tid & 63;
    float a0 = 0.f, a1 = 0.f, a2 = 0.f, a3 = 0.f;
    const float* Weh = We + (size_t)h * 128 * HD + j;
#pragma unroll 4
    for (int e = 0; e < 128; e++) {
        float w = Weh[(size_t)e * HD];
        a0 += E0s[e] * w; a1 += E0s[128 + e] * w;
        a2 += E0s[256 + e] * w; a3 += E0s[384 + e] * w;
    }
    g_E1b[((size_t)h * MM + m0 + 0) * HD + j] = __float2bfloat16(a0);
    g_E1b[((size_t)h * MM + m0 + 1) * HD + j] = __float2bfloat16(a1);
    g_E1b[((size_t)h * MM + m0 + 2) * HD + j] = __float2bfloat16(a2);
    g_E1b[((size_t)h * MM + m0 + 3) * HD + j] = __float2bfloat16(a3);

    float av = a[h * HD + j];
    float p0 = a0 * av, p1 = a1 * av, p2 = a2 * av, p3 = a3 * av;
#pragma unroll
    for (int o = 16; o; o >>= 1) {
        p0 += __shfl_xor_sync(0xffffffffu, p0, o);
        p1 += __shfl_xor_sync(0xffffffffu, p1, o);
        p2 += __shfl_xor_sync(0xffffffffu, p2, o);
        p3 += __shfl_xor_sync(0xffffffffu, p3, o);
    }
    int lane = tid & 31, w = tid >> 5;
    if (lane == 0) { dpart[w][0] = p0; dpart[w][1] = p1; dpart[w][2] = p2; dpart[w][3] = p3; }
    __syncthreads();
    if (tid < 16) {
        int h2 = tid >> 2, i2 = tid & 3;
        g_d[h2 * MM + m0 + i2] = (dpart[2 * h2][i2] + dpart[2 * h2 + 1][i2]) * LOG2E;
    }
}

// ============================ flash kernel ============================
// block = 128 n-rows x 1 head, 8 warps (16 rows each). Stream m in 64-chunks.
// W fragments generated in-register (mask bits + lrelu + ex2), B fragments via
// ldmatrix.trans from a double-buffered E1 tile, Z via a 9th MMA with B = ones.
__global__ __launch_bounds__(256, 2) void k_flash() {
    __shared__ __align__(16) __nv_bfloat16 Et[2][64 * 72];   // 144B row stride
    __shared__ float dsh[2][64];

    const int t = threadIdx.x, lane = t & 31, wid = t >> 5;
    const int g = lane >> 2, tg = lane & 3;
    const int h = blockIdx.y;
    const int n0 = blockIdx.x * 128;
    const int rowa = n0 + wid * 16 + g, rowb = rowa + 8;
    const float sa = g_s[h * NN + rowa];
    const float sb = g_s[h * NN + rowb];

    float acc[9][4];
#pragma unroll
    for (int i = 0; i < 9; i++)
#pragma unroll
        for (int q = 0; q < 4; q++) acc[i][q] = 0.f;

    const __nv_bfloat16* E1h = g_E1b + (size_t)h * MM * HD;
    const float* dh = g_d + h * MM;
    const uint32_t et0 = smem_u32(&Et[0][0]);
    const int lrow = lane & 15;                 // ldmatrix row provider
    const int u0 = t, u1 = t + 256;             // tile load indices
    const int lr0 = u0 >> 3, lc0 = (u0 & 7) * 8;
    const int lr1 = u1 >> 3, lc1 = (u1 & 7) * 8;
    const uint32_t bones = 0x3F803F80u;         // bf16x2 {1.0, 1.0}

    // preload tile 0
    {
        *(uint4*)((char*)&Et[0][0] + lr0 * 144 + (u0 & 7) * 16) =
            *(const uint4*)(E1h + (size_t)lr0 * HD + lc0);
        *(uint4*)((char*)&Et[0][0] + lr1 * 144 + (u1 & 7) * 16) =
            *(const uint4*)(E1h + (size_t)lr1 * HD + lc1);
        if (t < 16) *(float4*)&dsh[0][t * 4] = *(const float4*)(dh + t * 4);
    }
    __syncthreads();

    for (int ch = 0; ch < MM / 64; ch++) {
        const int b = ch & 1;
        const int m0 = ch * 64;
        const bool nxt = (ch + 1 < MM / 64);
        uint4 p0, p1; float4 pd;
        if (nxt) {
            const __nv_bfloat16* src = E1h + (size_t)(m0 + 64) * HD;
            p0 = *(const uint4*)(src + (size_t)lr0 * HD + lc0);
            p1 = *(const uint4*)(src + (size_t)lr1 * HD + lc1);
            if (t < 16) pd = *(const float4*)(dh + m0 + 64 + t * 4);
        }
        // A-mask words for this 64-m chunk (2 words per row)
        const uint32_t wa0 = g_AbT[(size_t)(m0 >> 5) * NN + rowa];
        const uint32_t wb0 = g_AbT[(size_t)(m0 >> 5) * NN + rowb];
        const uint32_t wa1 = g_AbT[(size_t)((m0 >> 5) + 1) * NN + rowa];
        const uint32_t wb1 = g_AbT[(size_t)((m0 >> 5) + 1) * NN + rowb];

        const uint32_t etb = et0 + b * 9216;

#pragma unroll
        for (int mc = 0; mc < 4; mc++) {
            const int mloc = mc * 16;
            const int sh = (mc & 1) * 16;
            const uint32_t ua = ((mc < 2) ? wa0 : wa1) >> (sh + 2 * tg);
            const uint32_t ub = ((mc < 2) ? wb0 : wb1) >> (sh + 2 * tg);
            const float2 d01 = *(const float2*)&dsh[b][mloc + 2 * tg];
            const float2 d23 = *(const float2*)&dsh[b][mloc + 2 * tg + 8];

            float xa0 = sa + d01.x, xa1 = sa + d01.y, xa2 = sa + d23.x, xa3 = sa + d23.y;
            float xb0 = sb + d01.x, xb1 = sb + d01.y, xb2 = sb + d23.x, xb3 = sb + d23.y;
            xa0 = fmaxf(xa0, 0.2f * xa0); xa1 = fmaxf(xa1, 0.2f * xa1);
            xa2 = fmaxf(xa2, 0.2f * xa2); xa3 = fmaxf(xa3, 0.2f * xa3);
            xb0 = fmaxf(xb0, 0.2f * xb0); xb1 = fmaxf(xb1, 0.2f * xb1);
            xb2 = fmaxf(xb2, 0.2f * xb2); xb3 = fmaxf(xb3, 0.2f * xb3);
            float ea0 = ex2f(xa0), ea1 = ex2f(xa1), ea2 = ex2f(xa2), ea3 = ex2f(xa3);
            float eb0 = ex2f(xb0), eb1 = ex2f(xb1), eb2 = ex2f(xb2), eb3 = ex2f(xb3);
            ea0 = (ua & 1u)   ? ea0 : 0.f;  ea1 = (ua & 2u)   ? ea1 : 0.f;
            ea2 = (ua & 256u) ? ea2 : 0.f;  ea3 = (ua & 512u) ? ea3 : 0.f;
            eb0 = (ub & 1u)   ? eb0 : 0.f;  eb1 = (ub & 2u)   ? eb1 : 0.f;
            eb2 = (ub & 256u) ? eb2 : 0.f;  eb3 = (ub & 512u) ? eb3 : 0.f;

            const uint32_t a0 = pack_bf2(ea0, ea1);
            const uint32_t a1 = pack_bf2(eb0, eb1);
            const uint32_t a2 = pack_bf2(ea2, ea3);
            const uint32_t a3 = pack_bf2(eb2, eb3);

            MMA16816(acc[8], a0, a1, a2, a3, bones, bones);   // Z

            const uint32_t rb = etb + (mloc + lrow) * 144;
#pragma unroll
            for (int j = 0; j < 8; j++) {
                uint32_t f0, f1;
                asm volatile("ldmatrix.sync.aligned.m8n8.x2.trans.shared.b16 {%0,%1}, [%2];"
                             : "=r"(f0), "=r"(f1) : "r"(rb + j * 16));
                MMA16816(acc[j], a0, a1, a2, a3, f0, f1);
            }
        }

        if (nxt) {
            char* dst = (char*)&Et[b ^ 1][0];
            *(uint4*)(dst + lr0 * 144 + (u0 & 7) * 16) = p0;
            *(uint4*)(dst + lr1 * 144 + (u1 & 7) * 16) = p1;
            if (t < 16) *(float4*)&dsh[b ^ 1][t * 4] = pd;
        }
        __syncthreads();
    }

    // epilogue: per-head partials (race-free, each (h,n) owned by one block)
    float* npa = &g_np[h][rowa][0];
    float* npb = &g_np[h][rowb][0];
#pragma unroll
    for (int j = 0; j < 8; j++) {
        *(float2*)(npa + j * 8 + 2 * tg) = make_float2(acc[j][0], acc[j][1]);
        *(float2*)(npb + j * 8 + 2 * tg) = make_float2(acc[j][2], acc[j][3]);
    }
    if (tg == 0) { g_zp[h][rowa] = acc[8][0]; g_zp[h][rowb] = acc[8][2]; }
}

// combine heads: mean(num/Z) then softmax over 64 -> out
__global__ void k_comb(float* __restrict__ out) {
    int warp = threadIdx.x >> 5, lane = threadIdx.x & 31;
    int n = blockIdx.x * 8 + warp;
    float v0 = 0.f, v1 = 0.f;
#pragma unroll
    for (int h = 0; h < NH; h++) {
        float inv = 1.0f / g_zp[h][n];
        v0 += g_np[h][n][lane] * inv;
        v1 += g_np[h][n][lane + 32] * inv;
    }
    v0 *= 0.25f; v1 *= 0.25f;
    float mx = fmaxf(v0, v1);
#pragma unroll
    for (int o = 16; o; o >>= 1) mx = fmaxf(mx, __shfl_xor_sync(0xffffffffu, mx, o));
    float e0 = __expf(v0 - mx), e1 = __expf(v1 - mx);
    float s = e0 + e1;
#pragma unroll
    for (int o = 16; o; o >>= 1) s += __shfl_xor_sync(0xffffffffu, s, o);
    float r = 1.0f / s;
    out[(size_t)n * HD + lane] = e0 * r;
    out[(size_t)n * HD + 32 + lane] = e1 * r;
}

// ============================ launch ============================
extern "C" void kernel_launch(void* const* d_in, const int* in_sizes, int n_in,
                              void* d_out, int out_size) {
    const float* F0 = (const float*)d_in[0];
    const float* E0 = (const float*)d_in[1];
    const int*   A  = (const int*)d_in[2];
    const float* Wf = (const float*)d_in[3];
    const float* We = (const float*)d_in[4];
    const float* a  = (const float*)d_in[5];
    float* out = (float*)d_out;
    (void)in_sizes; (void)n_in; (void)out_size;

    k_pack<<<1024, 256>>>(A);
    k_wfa<<<1, 512>>>(Wf, a);
    k_s<<<4096, 256>>>(F0);
    k_e1<<<MM / 4, 256>>>(E0, We, a);
    k_flash<<<dim3(NN / 128, NH), 256>>>();
    k_comb<<<NN / 8, 256>>>(out);
}

// round 4
// speedup vs baseline: 8.2256x; 1.2857x over previous
#include <cuda_runtime.h>
#include <cuda_fp16.h>
#include <cstdint>

#define NN 8192
#define MM 8192
#define HD 64
#define NH 4
#define LOG2E 1.4426950408889634f

// ---- scratch (device globals; no allocations allowed) ----
__device__ float g_s[NH * NN];                              // pre-scaled by log2e
__device__ float g_d[NH * MM];                              // pre-scaled by log2e
__device__ float g_wfa[NH * 128];
__device__ __align__(16) __half g_E1h[(size_t)NH * MM * HD]; // [h][m][j] 4MB
__device__ uint32_t g_AbT[(size_t)(MM / 32) * NN];          // [m/32][n] 8MB
__device__ float g_np[NH][NN][HD];                          // per-head numerators 8MB
__device__ float g_zp[NH][NN];                              // per-head Z

__device__ __forceinline__ uint32_t smem_u32(const void* p) {
    uint32_t a;
    asm("{ .reg .u64 t; cvta.to.shared.u64 t, %1; cvt.u32.u64 %0, t; }" : "=r"(a) : "l"(p));
    return a;
}
__device__ __forceinline__ uint32_t hadd2u(uint32_t a, uint32_t b) {
    uint32_t r; asm("add.f16x2 %0,%1,%2;" : "=r"(r) : "r"(a), "r"(b)); return r;
}
__device__ __forceinline__ uint32_t hmul2u(uint32_t a, uint32_t b) {
    uint32_t r; asm("mul.f16x2 %0,%1,%2;" : "=r"(r) : "r"(a), "r"(b)); return r;
}
__device__ __forceinline__ uint32_t hmax2u(uint32_t a, uint32_t b) {
    uint32_t r; asm("max.f16x2 %0,%1,%2;" : "=r"(r) : "r"(a), "r"(b)); return r;
}
__device__ __forceinline__ uint32_t ex2h2(uint32_t a) {
    uint32_t r; asm("ex2.approx.f16x2 %0,%1;" : "=r"(r) : "r"(a)); return r;
}
// leaky_relu then exp2 on packed f16x2
__device__ __forceinline__ uint32_t wgen(uint32_t x) {
    return ex2h2(hmax2u(x, hmul2u(x, 0x32663266u)));   // 0x3266 = 0.2f16
}
// mask from 2 bits (bit0 -> low half, bit1 -> high half)
__device__ __forceinline__ uint32_t mk2(uint32_t u) {
    return (u & 1u) * 0xFFFFu + (u & 2u) * 0x7FFF8000u;
}
#define MMA16816(acc, a0, a1, a2, a3, b0, b1)                                  \
    asm volatile("mma.sync.aligned.m16n8k16.row.col.f32.f16.f16.f32 "          \
                 "{%0,%1,%2,%3}, {%4,%5,%6,%7}, {%8,%9}, {%0,%1,%2,%3};"       \
                 : "+f"(acc[0]), "+f"(acc[1]), "+f"(acc[2]), "+f"(acc[3])      \
                 : "r"(a0), "r"(a1), "r"(a2), "r"(a3), "r"(b0), "r"(b1))

// ============================ stage kernels ============================
// Pack A -> transposed bitmask. 4 independent rows per warp-iteration (MLP=4).
__global__ void k_pack(const int* __restrict__ A) {
    int lane = threadIdx.x & 31;
    int gw = (blockIdx.x * blockDim.x + threadIdx.x) >> 5;
    int nw = (gridDim.x * blockDim.x) >> 5;
    for (int idx = gw; idx < (MM / 32) * (NN / 4); idx += nw) {
        int w = idx & 255;           // MM/32 = 256
        int n4 = idx >> 8;
        const int* base = A + (size_t)(n4 * 4) * MM + w * 32 + lane;
        int v0 = base[0];
        int v1 = base[MM];
        int v2 = base[2 * MM];
        int v3 = base[3 * MM];
        uint32_t b0 = __ballot_sync(0xffffffffu, v0 > 0);
        uint32_t b1 = __ballot_sync(0xffffffffu, v1 > 0);
        uint32_t b2 = __ballot_sync(0xffffffffu, v2 > 0);
        uint32_t b3 = __ballot_sync(0xffffffffu, v3 > 0);
        if (lane == 0) {
            uint32_t* dst = g_AbT + (size_t)w * NN + n4 * 4;
            dst[0] = b0; dst[1] = b1; dst[2] = b2; dst[3] = b3;
        }
    }
}

// wfa[h,f] = sum_d Wf[h,f,d] * a[h,d]
__global__ void k_wfa(const float* __restrict__ Wf, const float* __restrict__ a) {
    int tid = threadIdx.x;
    if (tid < NH * 128) {
        int h = tid >> 7, f = tid & 127;
        const float* wp = Wf + ((size_t)h * 128 + f) * HD;
        const float* ap = a + h * HD;
        float s = 0.f;
#pragma unroll 8
        for (int d = 0; d < HD; d++) s += wp[d] * ap[d];
        g_wfa[tid] = s;
    }
}

// s[h,n] = (F0[n,:] . wfa[h,:]) * log2e
__global__ void k_s(const float* __restrict__ F0) {
    int warp = threadIdx.x >> 5, lane = threadIdx.x & 31;
    int gw = blockIdx.x * 8 + warp;
    int n = gw & (NN - 1), h = gw >> 13;
    const float* fp = F0 + (size_t)n * 128;
    const float* wp = g_wfa + h * 128;
    float s = 0.f;
#pragma unroll
    for (int k = 0; k < 4; k++) { int f = lane + k * 32; s += fp[f] * wp[f]; }
#pragma unroll
    for (int o = 16; o; o >>= 1) s += __shfl_xor_sync(0xffffffffu, s, o);
    if (lane == 0) g_s[h * NN + n] = s * LOG2E;
}

// E1h[h][m][j] (f16) and d[h][m]*log2e. 8 m-rows per block, E0 transposed in smem.
__global__ __launch_bounds__(256) void k_e1(const float* __restrict__ E0,
                                            const float* __restrict__ We,
                                            const float* __restrict__ a) {
    __shared__ float E0t[128 * 12];      // [e][r], stride 12 (16B-aligned float4)
    __shared__ float dpart[8][8];
    int m0 = blockIdx.x * 8;
    int tid = threadIdx.x;
#pragma unroll
    for (int k = 0; k < 4; k++) {
        int idx = tid + k * 256;         // 1024 elements
        int e = idx & 127, r = idx >> 7;
        E0t[e * 12 + r] = E0[(size_t)(m0 + r) * 128 + e];
    }
    __syncthreads();

    int h = tid >> 6, j = tid & 63;
    float acc[8];
#pragma unroll
    for (int r = 0; r < 8; r++) acc[r] = 0.f;
    const float* Weh = We + (size_t)h * 128 * HD + j;
#pragma unroll 4
    for (int e = 0; e < 128; e++) {
        float w = Weh[(size_t)e * HD];
        float4 r03 = *(const float4*)&E0t[e * 12];
        float4 r47 = *(const float4*)&E0t[e * 12 + 4];
        acc[0] += r03.x * w; acc[1] += r03.y * w;
        acc[2] += r03.z * w; acc[3] += r03.w * w;
        acc[4] += r47.x * w; acc[5] += r47.y * w;
        acc[6] += r47.z * w; acc[7] += r47.w * w;
    }
#pragma unroll
    for (int r = 0; r < 8; r++)
        g_E1h[((size_t)h * MM + m0 + r) * HD + j] = __float2half_rn(acc[r]);

    float av = a[h * HD + j];
    float p[8];
#pragma unroll
    for (int r = 0; r < 8; r++) p[r] = acc[r] * av;
#pragma unroll
    for (int o = 16; o; o >>= 1)
#pragma unroll
        for (int r = 0; r < 8; r++) p[r] += __shfl_xor_sync(0xffffffffu, p[r], o);
    int lane = tid & 31, w = tid >> 5;
    if (lane == 0)
#pragma unroll
        for (int r = 0; r < 8; r++) dpart[w][r] = p[r];
    __syncthreads();
    if (tid < 32) {
        int h2 = tid >> 3, r = tid & 7;
        g_d[h2 * MM + m0 + r] = (dpart[2 * h2][r] + dpart[2 * h2 + 1][r]) * LOG2E;
    }
}

// ============================ flash kernel ============================
// block = 128 n-rows x 1 head, 8 warps (16 rows each). Stream m in 64-chunks.
// Packed f16x2 W-generation directly into MMA A-fragments; B via ldmatrix.x4;
// Z via a 9th MMA with B = ones.
__global__ __launch_bounds__(256, 2) void k_flash() {
    __shared__ __align__(16) __half Et[2][64 * 72];   // 144B row stride
    __shared__ uint32_t dsh[2][32];                   // f16x2 d-pairs

    const int t = threadIdx.x, lane = t & 31, wid = t >> 5;
    const int g = lane >> 2, tg = lane & 3;
    const int h = blockIdx.y;
    const int n0 = blockIdx.x * 128;
    const int rowa = n0 + wid * 16 + g, rowb = rowa + 8;
    const float saf = g_s[h * NN + rowa];
    const float sbf = g_s[h * NN + rowb];
    __half2 sa2h = __floats2half2_rn(saf, saf);
    __half2 sb2h = __floats2half2_rn(sbf, sbf);
    const uint32_t sa2 = *(uint32_t*)&sa2h, sb2 = *(uint32_t*)&sb2h;

    float acc[9][4];
#pragma unroll
    for (int i = 0; i < 9; i++)
#pragma unroll
        for (int q = 0; q < 4; q++) acc[i][q] = 0.f;

    const __half* E1p = g_E1h + (size_t)h * MM * HD;
    const float* dh = g_d + h * MM;
    const uint32_t et0 = smem_u32(&Et[0][0]);
    const int lr16 = lane & 15, ct = lane >> 4;       // ldmatrix.x4 mapping
    const int u0 = t, u1 = t + 256;                   // tile load indices
    const int lr0 = u0 >> 3, lc0 = (u0 & 7) * 8;
    const int lr1 = u1 >> 3, lc1 = (u1 & 7) * 8;
    const uint32_t bones = 0x3C003C00u;               // f16x2 {1,1}

    // preload tile 0 + d 0
    {
        *(uint4*)((char*)&Et[0][0] + lr0 * 144 + (u0 & 7) * 16) =
            *(const uint4*)(E1p + (size_t)lr0 * HD + lc0);
        *(uint4*)((char*)&Et[0][0] + lr1 * 144 + (u1 & 7) * 16) =
            *(const uint4*)(E1p + (size_t)lr1 * HD + lc1);
        if (t < 16) {
            float4 dv = *(const float4*)(dh + t * 4);
            __half2 q0 = __floats2half2_rn(dv.x, dv.y);
            __half2 q1 = __floats2half2_rn(dv.z, dv.w);
            dsh[0][2 * t] = *(uint32_t*)&q0;
            dsh[0][2 * t + 1] = *(uint32_t*)&q1;
        }
    }
    // preload masks for chunk 0
    uint32_t wa0 = g_AbT[rowa], wa1 = g_AbT[(size_t)NN + rowa];
    uint32_t wb0 = g_AbT[rowb], wb1 = g_AbT[(size_t)NN + rowb];
    __syncthreads();

    for (int ch = 0; ch < MM / 64; ch++) {
        const int b = ch & 1;
        const int m0 = ch * 64;
        const bool nxt = (ch + 1 < MM / 64);
        uint4 p0, p1; float4 pd;
        uint32_t na0, na1, nb0, nb1;
        if (nxt) {
            const __half* src = E1p + (size_t)(m0 + 64) * HD;
            p0 = *(const uint4*)(src + (size_t)lr0 * HD + lc0);
            p1 = *(const uint4*)(src + (size_t)lr1 * HD + lc1);
            if (t < 16) pd = *(const float4*)(dh + m0 + 64 + t * 4);
            const size_t wbase = (size_t)((m0 >> 5) + 2) * NN;
            na0 = g_AbT[wbase + rowa];       na1 = g_AbT[wbase + NN + rowa];
            nb0 = g_AbT[wbase + rowb];       nb1 = g_AbT[wbase + NN + rowb];
        }

        const uint32_t etb = et0 + b * 9216;

#pragma unroll
        for (int mc = 0; mc < 4; mc++) {
            const int mloc = mc * 16;
            const uint32_t dp0 = dsh[b][mc * 8 + tg];
            const uint32_t dp1 = dsh[b][mc * 8 + tg + 4];
            const int sh = ((mc & 1) << 4) + 2 * tg;
            uint32_t ua = ((mc < 2) ? wa0 : wa1) >> sh;
            uint32_t ub = ((mc < 2) ? wb0 : wb1) >> sh;

            uint32_t a0 = wgen(hadd2u(sa2, dp0)) & mk2(ua);
            uint32_t a1 = wgen(hadd2u(sb2, dp0)) & mk2(ub);
            uint32_t a2 = wgen(hadd2u(sa2, dp1)) & mk2(ua >> 8);
            uint32_t a3 = wgen(hadd2u(sb2, dp1)) & mk2(ub >> 8);

            MMA16816(acc[8], a0, a1, a2, a3, bones, bones);   // Z

            const uint32_t rb = etb + (mloc + lr16) * 144 + ct * 16;
#pragma unroll
            for (int jj = 0; jj < 4; jj++) {
                uint32_t f0, f1, f2, f3;
                asm volatile("ldmatrix.sync.aligned.m8n8.x4.trans.shared.b16 "
                             "{%0,%1,%2,%3}, [%4];"
                             : "=r"(f0), "=r"(f1), "=r"(f2), "=r"(f3)
                             : "r"(rb + jj * 32));
                MMA16816(acc[2 * jj],     a0, a1, a2, a3, f0, f1);
                MMA16816(acc[2 * jj + 1], a0, a1, a2, a3, f2, f3);
            }
        }

        if (nxt) {
            char* dst = (char*)&Et[b ^ 1][0];
            *(uint4*)(dst + lr0 * 144 + (u0 & 7) * 16) = p0;
            *(uint4*)(dst + lr1 * 144 + (u1 & 7) * 16) = p1;
            if (t < 16) {
                __half2 q0 = __floats2half2_rn(pd.x, pd.y);
                __half2 q1 = __floats2half2_rn(pd.z, pd.w);
                dsh[b ^ 1][2 * t] = *(uint32_t*)&q0;
                dsh[b ^ 1][2 * t + 1] = *(uint32_t*)&q1;
            }
            wa0 = na0; wa1 = na1; wb0 = nb0; wb1 = nb1;
        }
        __syncthreads();
    }

    // epilogue: per-head partials (race-free, each (h,n) owned by one block)
    float* npa = &g_np[h][rowa][0];
    float* npb = &g_np[h][rowb][0];
#pragma unroll
    for (int j = 0; j < 8; j++) {
        *(float2*)(npa + j * 8 + 2 * tg) = make_float2(acc[j][0], acc[j][1]);
        *(float2*)(npb + j * 8 + 2 * tg) = make_float2(acc[j][2], acc[j][3]);
    }
    if (tg == 0) { g_zp[h][rowa] = acc[8][0]; g_zp[h][rowb] = acc[8][2]; }
}

// combine heads: mean(num/Z) then softmax over 64 -> out
__global__ void k_comb(float* __restrict__ out) {
    int warp = threadIdx.x >> 5, lane = threadIdx.x & 31;
    int n = blockIdx.x * 8 + warp;
    float v0 = 0.f, v1 = 0.f;
#pragma unroll
    for (int h = 0; h < NH; h++) {
        float inv = 1.0f / g_zp[h][n];
        v0 += g_np[h][n][lane] * inv;
        v1 += g_np[h][n][lane + 32] * inv;
    }
    v0 *= 0.25f; v1 *= 0.25f;
    float mx = fmaxf(v0, v1);
#pragma unroll
    for (int o = 16; o; o >>= 1) mx = fmaxf(mx, __shfl_xor_sync(0xffffffffu, mx, o));
    float e0 = __expf(v0 - mx), e1 = __expf(v1 - mx);
    float s = e0 + e1;
#pragma unroll
    for (int o = 16; o; o >>= 1) s += __shfl_xor_sync(0xffffffffu, s, o);
    float r = 1.0f / s;
    out[(size_t)n * HD + lane] = e0 * r;
    out[(size_t)n * HD + 32 + lane] = e1 * r;
}

// ============================ launch ============================
extern "C" void kernel_launch(void* const* d_in, const int* in_sizes, int n_in,
                              void* d_out, int out_size) {
    const float* F0 = (const float*)d_in[0];
    const float* E0 = (const float*)d_in[1];
    const int*   A  = (const int*)d_in[2];
    const float* Wf = (const float*)d_in[3];
    const float* We = (const float*)d_in[4];
    const float* a  = (const float*)d_in[5];
    float* out = (float*)d_out;
    (void)in_sizes; (void)n_in; (void)out_size;

    k_pack<<<2048, 256>>>(A);
    k_wfa<<<1, 512>>>(Wf, a);
    k_s<<<4096, 256>>>(F0);
    k_e1<<<MM / 8, 256>>>(E0, We, a);
    k_flash<<<dim3(NN / 128, NH), 256>>>();
    k_comb<<<NN / 8, 256>>>(out);
}